// round 10
// baseline (speedup 1.0000x reference)
#include <cuda_runtime.h>
#include <cstdint>

#define N_NODES 2048
#define F_FEAT  64
#define H_HID   64
#define C_OUT   8
#define JCHUNK  512
#define NSPLIT  (N_NODES / JCHUNK)   // 4 j-chunks
#define FSPLIT  2
#define FPER    (F_FEAT / FSPLIT)    // 32 features per split

// partial g, per f-half: [s][c][j]  (pure writes -> replay-safe)
__device__ __align__(16) float g_part[FSPLIT * C_OUT * N_NODES];
// PWL table for m(d), built once by g_kernel block (0,0) warp 0
__device__ float g_bpG[64];
__device__ float g_AG[65];
__device__ float g_BG[65];

// fma-pipe reciprocal: magic init + 2 Newton iterations (rel err ~6e-6)
__device__ __forceinline__ float frcp_nr(float y) {
    float r = __int_as_float(0x7EF311C3 - __float_as_int(y));
    r = r * fmaf(-y, r, 2.0f);
    r = r * fmaf(-y, r, 2.0f);
    return r;
}

// ---------------------------------------------------------------------------
// g kernel: grid (256 rowgroups, 2 f-halves) x 128 threads (4 warps).
// Each warp: 2 rows x 32 features. 512 blocks -> ~3.5 blocks/SM, enough TLP
// to sit on the FFMA floor (~4.2us). L1 weight traffic (amortization 2) is
// below the FMA floor.
// g_part[s][c][j] = sum_{f in half s} sum_h relu(x*W1+b1)*W2 + sum_{f} b2
// Block (0,0) warp 0 additionally builds the PWL table for m(d).
// fs==0 blocks zero `out` (main accumulates atomically; replay-safe).
// ---------------------------------------------------------------------------
__global__ void __launch_bounds__(128) g_kernel(
        const float* __restrict__ x,
        const float* __restrict__ W1,
        const float* __restrict__ b1,
        const float* __restrict__ W2,
        const float* __restrict__ b2,
        const float* __restrict__ Wm1,
        const float* __restrict__ bm1,
        const float* __restrict__ Wm2,
        const float* __restrict__ bm2,
        float* __restrict__ out) {
    __shared__ float s_bias[C_OUT];
    __shared__ float w_t[64], s_bp[64], s_dA[64], s_dB[64];

    int tid  = threadIdx.x;
    int lane = tid & 31;
    int warp = tid >> 5;
    int by   = blockIdx.x;
    int fs   = blockIdx.y;
    int fbase = fs * FPER;

    // zero out (poisoned by harness; re-zeroed every graph replay)
    if (fs == 0 && tid < 64)
        out[by * 64 + tid] = 0.f;    // 256 blocks x 64 = 16384 = N*C

    // half-local bias: s_bias[c] = sum_{f in half} b2[f,c]
    if (tid < C_OUT) {
        float s = 0.f;
#pragma unroll
        for (int fi = 0; fi < FPER; fi++)
            s += b2[(fbase + fi) * C_OUT + tid];
        s_bias[tid] = s;
    }

    // ---- PWL table build (block (0,0), warp 0 only) ----
    if (by == 0 && fs == 0 && warp == 0) {
        float t[2], da[2], db[2], bA[2], bB[2];
#pragma unroll
        for (int e = 0; e < 2; e++) {
            int h = lane + e * 32;
            float a = Wm1[h], b = bm1[h], c = Wm2[h];
            float tt, vda = 0.f, vdb = 0.f, vbA = 0.f, vbB = 0.f;
            if (a != 0.f) {
                tt = -b / a;
                float pa = a * c, pb = b * c;
                if (a > 0.f) { vda = pa;  vdb = pb; }
                else         { vda = -pa; vdb = -pb; vbA = pa; vbB = pb; }
            } else {
                tt = __int_as_float(0x7f800000);
                if (b > 0.f) vbB = b * c;
            }
            t[e] = tt; da[e] = vda; db[e] = vdb; bA[e] = vbA; bB[e] = vbB;
        }
        w_t[lane] = t[0]; w_t[lane + 32] = t[1];
        __syncwarp();

        int rk[2] = {0, 0};
        for (int k = 0; k < 64; k++) {
            float o = w_t[k];
            rk[0] += (o < t[0]) || (o == t[0] && k < lane);
            rk[1] += (o < t[1]) || (o == t[1] && k < lane + 32);
        }
        s_bp[rk[0]] = t[0]; s_dA[rk[0]] = da[0]; s_dB[rk[0]] = db[0];
        s_bp[rk[1]] = t[1]; s_dA[rk[1]] = da[1]; s_dB[rk[1]] = db[1];
        __syncwarp();

        float ra = bA[0] + bA[1], rb = bB[0] + bB[1];
#pragma unroll
        for (int o = 16; o; o >>= 1) {
            ra += __shfl_xor_sync(0xffffffffu, ra, o);
            rb += __shfl_xor_sync(0xffffffffu, rb, o);
        }
        float A0 = ra, B0 = rb + bm2[0];

        float a0 = s_dA[2 * lane], a1 = s_dA[2 * lane + 1];
        float b0 = s_dB[2 * lane], b1v = s_dB[2 * lane + 1];
        float sa = a0 + a1, sb = b0 + b1v;
        float ia = sa, ib = sb;
#pragma unroll
        for (int o = 1; o < 32; o <<= 1) {
            float ua = __shfl_up_sync(0xffffffffu, ia, o);
            float ub = __shfl_up_sync(0xffffffffu, ib, o);
            if (lane >= o) { ia += ua; ib += ub; }
        }
        float ea = ia - sa, eb = ib - sb;   // exclusive prefix
        if (lane == 0) { g_AG[0] = A0; g_BG[0] = B0; }
        g_AG[2 * lane + 1] = A0 + ea + a0;
        g_BG[2 * lane + 1] = B0 + eb + b0;
        g_AG[2 * lane + 2] = A0 + ea + a0 + a1;
        g_BG[2 * lane + 2] = B0 + eb + b0 + b1v;
        g_bpG[2 * lane]     = s_bp[2 * lane];
        g_bpG[2 * lane + 1] = s_bp[2 * lane + 1];
    }

    // ---- per-feature NAM accumulation: 2 rows x 32 features per warp ----
    int r0 = by * 8 + warp * 2;
    int h0 = lane, h1 = lane + 32;

    float xr0 = x[r0 * F_FEAT + fbase + lane];
    float xr1 = x[(r0 + 1) * F_FEAT + fbase + lane];

    float acc0[C_OUT], acc1[C_OUT];
#pragma unroll
    for (int c = 0; c < C_OUT; c++) { acc0[c] = 0.f; acc1[c] = 0.f; }

#pragma unroll 4
    for (int fi = 0; fi < FPER; fi++) {
        int f = fbase + fi;
        float w1a = W1[f * 64 + h0], w1b = W1[f * 64 + h1];
        float c1a = b1[f * 64 + h0], c1b = b1[f * 64 + h1];
        const float4* wa = (const float4*)(W2 + (size_t)(f * 64 + h0) * 8);
        const float4* wb = (const float4*)(W2 + (size_t)(f * 64 + h1) * 8);
        float4 a0 = wa[0], a1 = wa[1];
        float4 b0v = wb[0], b1w = wb[1];

        float xv0 = __shfl_sync(0xffffffffu, xr0, fi);
        float xv1 = __shfl_sync(0xffffffffu, xr1, fi);

        float h0a = fmaxf(fmaf(xv0, w1a, c1a), 0.f);
        float h0b = fmaxf(fmaf(xv0, w1b, c1b), 0.f);
        float h1a = fmaxf(fmaf(xv1, w1a, c1a), 0.f);
        float h1b = fmaxf(fmaf(xv1, w1b, c1b), 0.f);

        acc0[0] = fmaf(h0a, a0.x, fmaf(h0b, b0v.x, acc0[0]));
        acc0[1] = fmaf(h0a, a0.y, fmaf(h0b, b0v.y, acc0[1]));
        acc0[2] = fmaf(h0a, a0.z, fmaf(h0b, b0v.z, acc0[2]));
        acc0[3] = fmaf(h0a, a0.w, fmaf(h0b, b0v.w, acc0[3]));
        acc0[4] = fmaf(h0a, a1.x, fmaf(h0b, b1w.x, acc0[4]));
        acc0[5] = fmaf(h0a, a1.y, fmaf(h0b, b1w.y, acc0[5]));
        acc0[6] = fmaf(h0a, a1.z, fmaf(h0b, b1w.z, acc0[6]));
        acc0[7] = fmaf(h0a, a1.w, fmaf(h0b, b1w.w, acc0[7]));

        acc1[0] = fmaf(h1a, a0.x, fmaf(h1b, b0v.x, acc1[0]));
        acc1[1] = fmaf(h1a, a0.y, fmaf(h1b, b0v.y, acc1[1]));
        acc1[2] = fmaf(h1a, a0.z, fmaf(h1b, b0v.z, acc1[2]));
        acc1[3] = fmaf(h1a, a0.w, fmaf(h1b, b0v.w, acc1[3]));
        acc1[4] = fmaf(h1a, a1.x, fmaf(h1b, b1w.x, acc1[4]));
        acc1[5] = fmaf(h1a, a1.y, fmaf(h1b, b1w.y, acc1[5]));
        acc1[6] = fmaf(h1a, a1.z, fmaf(h1b, b1w.z, acc1[6]));
        acc1[7] = fmaf(h1a, a1.w, fmaf(h1b, b1w.w, acc1[7]));
    }

#pragma unroll
    for (int c = 0; c < C_OUT; c++) {
#pragma unroll
        for (int o = 16; o; o >>= 1) {
            acc0[c] += __shfl_xor_sync(0xffffffffu, acc0[c], o);
            acc1[c] += __shfl_xor_sync(0xffffffffu, acc1[c], o);
        }
    }

    __syncthreads();   // s_bias ready
    if (lane == 0) {
#pragma unroll
        for (int c = 0; c < C_OUT; c++) {
            g_part[(fs * C_OUT + c) * N_NODES + r0]     = acc0[c] + s_bias[c];
            g_part[(fs * C_OUT + c) * N_NODES + r0 + 1] = acc1[c] + s_bias[c];
        }
    }
}

// ---------------------------------------------------------------------------
// Main kernel: out[i,c] += sum_{j in chunk} m(nd[i,j]/nm[i,j]) * g[j,c]
// Grid (128 rowgroups x 4 j-chunks) = 512 blocks, 4/SM (32 warps/SM).
// Two warp-uniform votes per iteration:
//   1) all nm == 1.0f  -> skip reciprocal entirely (d = nd)    [holds here]
//   2) min(d) > top bp -> single-segment FMA, no table lookup  [holds here]
// Both have fully general fallbacks (Newton rcp / binary search), so the
// kernel is correct for arbitrary inputs.
// ---------------------------------------------------------------------------
__global__ void __launch_bounds__(256, 4) main_kernel(
        const float* __restrict__ nd,
        const float* __restrict__ nm,
        float* __restrict__ out) {
    __shared__ float gTs[C_OUT * JCHUNK];   // 16KB

    int tid = threadIdx.x;
    int jbase = blockIdx.y * JCHUNK;

    // stage gT chunk: float4 loads, sum of the 2 f-half partials
    {
        const float4* g4 = (const float4*)g_part;
        const int half4 = (C_OUT * N_NODES) >> 2;
#pragma unroll
        for (int i = tid; i < (C_OUT * JCHUNK) >> 2; i += 256) {
            int c = i >> 7, j4 = i & 127;            // 128 float4 per c-row
            int off = ((c * N_NODES + jbase) >> 2) + j4;
            float4 a = g4[off];
            float4 b = g4[half4 + off];
            float4 s = make_float4(a.x + b.x, a.y + b.y, a.z + b.z, a.w + b.w);
            ((float4*)gTs)[i] = s;
        }
    }

    float top = __ldg(&g_bpG[63]);
    float A64 = __ldg(&g_AG[64]);
    float B64 = __ldg(&g_BG[64]);
    __syncthreads();

    int warp = tid >> 5, lane = tid & 31;
    int r0 = blockIdx.x * 16 + warp * 2;
    int r1 = r0 + 1;

    const float* d0p = nd + (size_t)r0 * N_NODES + jbase;
    const float* n0p = nm + (size_t)r0 * N_NODES + jbase;
    const float* d1p = nd + (size_t)r1 * N_NODES + jbase;
    const float* n1p = nm + (size_t)r1 * N_NODES + jbase;

    float acc0[C_OUT], acc1[C_OUT];
#pragma unroll
    for (int c = 0; c < C_OUT; c++) { acc0[c] = 0.f; acc1[c] = 0.f; }

    int jb = lane * 4;
    float4 dq0 = __ldcs((const float4*)(d0p + jb));
    float4 nq0 = __ldcs((const float4*)(n0p + jb));
    float4 dq1 = __ldcs((const float4*)(d1p + jb));
    float4 nq1 = __ldcs((const float4*)(n1p + jb));

#pragma unroll
    for (int it = 0; it < JCHUNK / 128; it++) {
        float4 cd0 = dq0, cn0 = nq0, cd1 = dq1, cn1 = nq1;
        int jn = jb + 128;
        if (it + 1 < JCHUNK / 128) {
            dq0 = __ldcs((const float4*)(d0p + jn));
            nq0 = __ldcs((const float4*)(n0p + jn));
            dq1 = __ldcs((const float4*)(d1p + jn));
            nq1 = __ldcs((const float4*)(n1p + jn));
        }

        float dv[8], m[8];

        // vote 1: all normalizers exactly 1 -> d = nd (no division)
        bool ones = (cn0.x == 1.f) & (cn0.y == 1.f) & (cn0.z == 1.f) &
                    (cn0.w == 1.f) & (cn1.x == 1.f) & (cn1.y == 1.f) &
                    (cn1.z == 1.f) & (cn1.w == 1.f);
        if (__all_sync(0xffffffffu, ones)) {
            dv[0] = cd0.x; dv[1] = cd0.y; dv[2] = cd0.z; dv[3] = cd0.w;
            dv[4] = cd1.x; dv[5] = cd1.y; dv[6] = cd1.z; dv[7] = cd1.w;
        } else {
            dv[0] = cd0.x * frcp_nr(cn0.x);
            dv[1] = cd0.y * frcp_nr(cn0.y);
            dv[2] = cd0.z * frcp_nr(cn0.z);
            dv[3] = cd0.w * frcp_nr(cn0.w);
            dv[4] = cd1.x * frcp_nr(cn1.x);
            dv[5] = cd1.y * frcp_nr(cn1.y);
            dv[6] = cd1.z * frcp_nr(cn1.z);
            dv[7] = cd1.w * frcp_nr(cn1.w);
        }

        // vote 2: all d above the top breakpoint -> single-segment FMA
        float mn = fminf(fminf(fminf(dv[0], dv[1]), fminf(dv[2], dv[3])),
                         fminf(fminf(dv[4], dv[5]), fminf(dv[6], dv[7])));

        if (__all_sync(0xffffffffu, mn > top)) {
#pragma unroll
            for (int t = 0; t < 8; t++)
                m[t] = fmaf(A64, dv[t], B64);
        } else {
#pragma unroll
            for (int t = 0; t < 8; t++) {
                float d = dv[t];
                int k = 0;
#pragma unroll
                for (int s = 32; s >= 1; s >>= 1)
                    if (__ldg(&g_bpG[k + s - 1]) < d) k += s;
                m[t] = fmaf(__ldg(&g_AG[k]), d, __ldg(&g_BG[k]));
            }
        }

#pragma unroll
        for (int c = 0; c < C_OUT; c++) {
            float4 gv = *(const float4*)(gTs + c * JCHUNK + jb);
            acc0[c] = fmaf(m[0], gv.x, acc0[c]);
            acc0[c] = fmaf(m[1], gv.y, acc0[c]);
            acc0[c] = fmaf(m[2], gv.z, acc0[c]);
            acc0[c] = fmaf(m[3], gv.w, acc0[c]);
            acc1[c] = fmaf(m[4], gv.x, acc1[c]);
            acc1[c] = fmaf(m[5], gv.y, acc1[c]);
            acc1[c] = fmaf(m[6], gv.z, acc1[c]);
            acc1[c] = fmaf(m[7], gv.w, acc1[c]);
        }
        jb = jn;
    }

#pragma unroll
    for (int c = 0; c < C_OUT; c++) {
#pragma unroll
        for (int o = 16; o; o >>= 1) {
            acc0[c] += __shfl_xor_sync(0xffffffffu, acc0[c], o);
            acc1[c] += __shfl_xor_sync(0xffffffffu, acc1[c], o);
        }
    }

    if (lane == 0) {
#pragma unroll
        for (int c = 0; c < C_OUT; c++) {
            atomicAdd(&out[r0 * C_OUT + c], acc0[c]);
            atomicAdd(&out[r1 * C_OUT + c], acc1[c]);
        }
    }
}

// ---------------------------------------------------------------------------
extern "C" void kernel_launch(void* const* d_in, const int* in_sizes, int n_in,
                              void* d_out, int out_size) {
    const float* x   = (const float*)d_in[0];
    const float* nd  = (const float*)d_in[1];
    const float* nm  = (const float*)d_in[2];
    const float* W1  = (const float*)d_in[3];
    const float* b1  = (const float*)d_in[4];
    const float* W2  = (const float*)d_in[5];
    const float* b2  = (const float*)d_in[6];
    const float* Wm1 = (const float*)d_in[7];
    const float* bm1 = (const float*)d_in[8];
    const float* Wm2 = (const float*)d_in[9];
    const float* bm2 = (const float*)d_in[10];
    float* out = (float*)d_out;

    dim3 ggrid(N_NODES / 8, FSPLIT);
    g_kernel<<<ggrid, 128>>>(x, W1, b1, W2, b2, Wm1, bm1, Wm2, bm2, out);

    dim3 mgrid(N_NODES / 16, NSPLIT);
    main_kernel<<<mgrid, 256>>>(nd, nm, out);
}